// round 8
// baseline (speedup 1.0000x reference)
#include <cuda_runtime.h>

// ---------------------------------------------------------------------------
// WindowAttention: x(2048,49,192) -> qkv gemm -> 6-head window attention with
// azimuthal + radial sinusoidal biases -> proj gemm.
// Round 4: correct fp32 baseline, tiled SGEMMs + fused per-(b,h) attention.
// ---------------------------------------------------------------------------

#define WH 7
#define WW 7
#define NWIN 49
#define NH 6
#define HD 32
#define DIM 192
#define BATCH 2048
#define MROWS (BATCH * NWIN)          // 100352
#define QK_SCALE 0.17677669529663687f // 32^-0.5
#define PI_F 3.14159265358979323846f

// Scratch (allocation-free rule: __device__ globals)
__device__ float g_q[(size_t)BATCH * NH * NWIN * HD];
__device__ float g_k[(size_t)BATCH * NH * NWIN * HD];
__device__ float g_v[(size_t)BATCH * NH * NWIN * HD];
__device__ float g_ctx[(size_t)MROWS * DIM];

// ---------------------------------------------------------------------------
// Tiled SGEMM: out[m][n] = sum_k A[m][k] * W[n][k] (+ bias[n])
// BM=128, BN=64, BK=16, 256 threads, 8x4 per-thread tile.
// QKV=true: A = x, epilogue scatters into g_q (scaled), g_k, g_v.
// QKV=false: A = g_ctx, epilogue writes d_out with bias.
// All dims divide tiles exactly (100352 = 784*128, 576 = 9*64, 192 = 3*64,
// K = 192 = 12*16) -> no bounds checks.
// ---------------------------------------------------------------------------
#define BM 128
#define BN 64
#define BK 16
#define TM 8
#define TN 4

template <bool QKV>
__global__ __launch_bounds__(256) void gemm_kernel(
    const float* __restrict__ Ain, const float* __restrict__ W,
    const float* __restrict__ bias, float* __restrict__ out)
{
    const float* A = QKV ? Ain : g_ctx;

    __shared__ float As[BK][BM];
    __shared__ float Bs[BK][BN];

    const int tid = threadIdx.x;
    const int ty = tid >> 4;        // 0..15
    const int tx = tid & 15;        // 0..15
    const int m0 = blockIdx.y * BM;
    const int n0 = blockIdx.x * BN;

    const int lrow = tid >> 2;          // 0..63
    const int lcol = (tid & 3) << 2;    // 0,4,8,12

    const float* Aptr = A + (size_t)(m0 + lrow) * DIM + lcol;
    const float* Wptr = W + (size_t)(n0 + lrow) * DIM + lcol;

    float acc[TM][TN];
#pragma unroll
    for (int i = 0; i < TM; i++)
#pragma unroll
        for (int j = 0; j < TN; j++) acc[i][j] = 0.0f;

    for (int kk = 0; kk < DIM; kk += BK) {
        float4 a0 = *(const float4*)(Aptr + kk);
        float4 a1 = *(const float4*)(Aptr + (size_t)64 * DIM + kk);
        float4 b0 = *(const float4*)(Wptr + kk);

        As[lcol + 0][lrow] = a0.x;
        As[lcol + 1][lrow] = a0.y;
        As[lcol + 2][lrow] = a0.z;
        As[lcol + 3][lrow] = a0.w;
        As[lcol + 0][lrow + 64] = a1.x;
        As[lcol + 1][lrow + 64] = a1.y;
        As[lcol + 2][lrow + 64] = a1.z;
        As[lcol + 3][lrow + 64] = a1.w;
        Bs[lcol + 0][lrow] = b0.x;
        Bs[lcol + 1][lrow] = b0.y;
        Bs[lcol + 2][lrow] = b0.z;
        Bs[lcol + 3][lrow] = b0.w;
        __syncthreads();

#pragma unroll
        for (int k = 0; k < BK; k++) {
            float4 av0 = *(const float4*)&As[k][ty * TM];
            float4 av1 = *(const float4*)&As[k][ty * TM + 4];
            float4 bv  = *(const float4*)&Bs[k][tx * TN];
            float a[TM] = {av0.x, av0.y, av0.z, av0.w, av1.x, av1.y, av1.z, av1.w};
            float b[TN] = {bv.x, bv.y, bv.z, bv.w};
#pragma unroll
            for (int i = 0; i < TM; i++)
#pragma unroll
                for (int j = 0; j < TN; j++)
                    acc[i][j] = fmaf(a[i], b[j], acc[i][j]);
        }
        __syncthreads();
    }

    const int m_base = m0 + ty * TM;
    const int n_base = n0 + tx * TN;

    if (QKV) {
#pragma unroll
        for (int i = 0; i < TM; i++) {
            int m = m_base + i;
            int b = m / NWIN;
            int nn = m - b * NWIN;
#pragma unroll
            for (int j = 0; j < TN; j++) {
                int n = n_base + j;
                float val = acc[i][j] + bias[n];
                int which = n / DIM;
                int rem = n - which * DIM;
                int h = rem >> 5;
                int d = rem & 31;
                size_t idx = (((size_t)b * NH + h) * NWIN + nn) * HD + d;
                if (which == 0)      g_q[idx] = val * QK_SCALE;
                else if (which == 1) g_k[idx] = val;
                else                 g_v[idx] = val;
            }
        }
    } else {
#pragma unroll
        for (int i = 0; i < TM; i++) {
            int m = m_base + i;
            float4 o;
            o.x = acc[i][0] + bias[n_base + 0];
            o.y = acc[i][1] + bias[n_base + 1];
            o.z = acc[i][2] + bias[n_base + 2];
            o.w = acc[i][3] + bias[n_base + 3];
            *(float4*)&out[(size_t)m * DIM + n_base] = o;
        }
    }
}

// ---------------------------------------------------------------------------
// Attention: one block per (head h, window b). 256 threads.
//   S = q*k^T (q pre-scaled) + A_phi(h) + A_r(b,h); softmax rows; O = P*V.
// Biases computed on the fly from (i,j) -> (radius, azimuth).
// ---------------------------------------------------------------------------
__global__ __launch_bounds__(256) void attn_kernel(
    const float* __restrict__ Dptr,
    const float* __restrict__ a_p, const float* __restrict__ b_p,
    const float* __restrict__ a_r, const float* __restrict__ b_r)
{
    const int h = blockIdx.x;
    const int b = blockIdx.y;
    const int tid = threadIdx.x;

    __shared__ float qs[NWIN * 33];
    __shared__ float ks[NWIN * 33];
    __shared__ float vs[NWIN * 33];
    __shared__ float S[NWIN * NWIN];
    __shared__ float t_ap[13], t_bp[13], t_ar[13], t_br[13];

    const size_t base = ((size_t)b * NH + h) * NWIN * HD;

    if (tid < 13) {
        t_ap[tid] = a_p[tid * NH + h];
        t_bp[tid] = b_p[tid * NH + h];
        t_ar[tid] = a_r[tid * NH + h];
        t_br[tid] = b_r[tid * NH + h];
    }
    for (int t = tid; t < NWIN * HD; t += 256) {
        int r = t >> 5, c = t & 31;
        qs[r * 33 + c] = g_q[base + t];
        ks[r * 33 + c] = g_k[base + t];
        vs[r * 33 + c] = g_v[base + t];
    }
    const float Db = Dptr[b];
    __syncthreads();

    // S = scores + biases
    for (int t = tid; t < NWIN * NWIN; t += 256) {
        int i = t / NWIN;
        int j = t - i * NWIN;
        const float* qr = qs + i * 33;
        const float* kr = ks + j * 33;
        float dot = 0.0f;
#pragma unroll
        for (int d = 0; d < HD; d++) dot = fmaf(qr[d], kr[d], dot);

        int ih = i / WW, iw = i - ih * WW;
        int jh = j / WW, jw = j - jh * WW;
        int rr = ih - jh;           // radius in [-6, 6]
        int az = iw - jw;           // azimuth in [-6, 6]
        int ridx = rr < 0 ? rr + 13 : rr;   // python-style wrap (mod 13)
        int aidx = az < 0 ? az + 13 : az;

        float sph, cph;
        sincosf((float)az * (2.0f * PI_F / 56.0f), &sph, &cph);
        float srr, crr;
        sincosf(Db * (float)rr * (2.0f * PI_F / 224.0f), &srr, &crr);

        S[t] = dot + t_ap[aidx] * cph + t_bp[aidx] * sph
                   + t_ar[ridx] * crr + t_br[ridx] * srr;
    }
    __syncthreads();

    // softmax: one warp per row
    const int warp = tid >> 5, lane = tid & 31;
    for (int row = warp; row < NWIN; row += 8) {
        float* Sr = S + row * NWIN;
        float v0 = Sr[lane];
        float v1 = (lane + 32 < NWIN) ? Sr[lane + 32] : -1e30f;
        float mx = fmaxf(v0, v1);
#pragma unroll
        for (int o = 16; o; o >>= 1)
            mx = fmaxf(mx, __shfl_xor_sync(0xffffffffu, mx, o));
        float e0 = expf(v0 - mx);
        float e1 = (lane + 32 < NWIN) ? expf(v1 - mx) : 0.0f;
        float sm = e0 + e1;
#pragma unroll
        for (int o = 16; o; o >>= 1)
            sm += __shfl_xor_sync(0xffffffffu, sm, o);
        float inv = 1.0f / sm;
        Sr[lane] = e0 * inv;
        if (lane + 32 < NWIN) Sr[lane + 32] = e1 * inv;
    }
    __syncthreads();

    // O = P * V -> ctx layout (b, n, h*32 + d) for the proj GEMM
    float* ctx = g_ctx + ((size_t)b * NWIN) * DIM + h * HD;
    for (int t = tid; t < NWIN * HD; t += 256) {
        int n = t >> 5, d = t & 31;
        const float* Pr = S + n * NWIN;
        float o = 0.0f;
#pragma unroll
        for (int m2 = 0; m2 < NWIN; m2++)
            o = fmaf(Pr[m2], vs[m2 * 33 + d], o);
        ctx[n * DIM + d] = o;
    }
}

// ---------------------------------------------------------------------------
extern "C" void kernel_launch(void* const* d_in, const int* in_sizes, int n_in,
                              void* d_out, int out_size)
{
    const float* x      = (const float*)d_in[0];
    const float* D      = (const float*)d_in[1];
    const float* qkv_w  = (const float*)d_in[2];
    const float* qkv_b  = (const float*)d_in[3];
    const float* proj_w = (const float*)d_in[4];
    const float* proj_b = (const float*)d_in[5];
    const float* a_p    = (const float*)d_in[6];
    const float* b_p    = (const float*)d_in[7];
    const float* a_r    = (const float*)d_in[8];
    const float* b_r    = (const float*)d_in[9];
    float* out = (float*)d_out;

    gemm_kernel<true><<<dim3(3 * DIM / BN, MROWS / BM), 256>>>(x, qkv_w, qkv_b, nullptr);
    attn_kernel<<<dim3(NH, BATCH), 256>>>(D, a_p, b_p, a_r, b_r);
    gemm_kernel<false><<<dim3(DIM / BN, MROWS / BM), 256>>>(nullptr, proj_w, proj_b, out);
}

// round 9
// speedup vs baseline: 1.0013x; 1.0013x over previous
#include <cuda_runtime.h>

// ---------------------------------------------------------------------------
// WindowAttention: x(2048,49,192) -> qkv gemm -> 6-head window attention with
// azimuthal + radial sinusoidal biases -> proj gemm.
// Round 4: correct fp32 baseline, tiled SGEMMs + fused per-(b,h) attention.
// ---------------------------------------------------------------------------

#define WH 7
#define WW 7
#define NWIN 49
#define NH 6
#define HD 32
#define DIM 192
#define BATCH 2048
#define MROWS (BATCH * NWIN)          // 100352
#define QK_SCALE 0.17677669529663687f // 32^-0.5
#define PI_F 3.14159265358979323846f

// Scratch (allocation-free rule: __device__ globals)
__device__ float g_q[(size_t)BATCH * NH * NWIN * HD];
__device__ float g_k[(size_t)BATCH * NH * NWIN * HD];
__device__ float g_v[(size_t)BATCH * NH * NWIN * HD];
__device__ float g_ctx[(size_t)MROWS * DIM];

// ---------------------------------------------------------------------------
// Tiled SGEMM: out[m][n] = sum_k A[m][k] * W[n][k] (+ bias[n])
// BM=128, BN=64, BK=16, 256 threads, 8x4 per-thread tile.
// QKV=true: A = x, epilogue scatters into g_q (scaled), g_k, g_v.
// QKV=false: A = g_ctx, epilogue writes d_out with bias.
// All dims divide tiles exactly (100352 = 784*128, 576 = 9*64, 192 = 3*64,
// K = 192 = 12*16) -> no bounds checks.
// ---------------------------------------------------------------------------
#define BM 128
#define BN 64
#define BK 16
#define TM 8
#define TN 4

template <bool QKV>
__global__ __launch_bounds__(256) void gemm_kernel(
    const float* __restrict__ Ain, const float* __restrict__ W,
    const float* __restrict__ bias, float* __restrict__ out)
{
    const float* A = QKV ? Ain : g_ctx;

    __shared__ float As[BK][BM];
    __shared__ float Bs[BK][BN];

    const int tid = threadIdx.x;
    const int ty = tid >> 4;        // 0..15
    const int tx = tid & 15;        // 0..15
    const int m0 = blockIdx.y * BM;
    const int n0 = blockIdx.x * BN;

    const int lrow = tid >> 2;          // 0..63
    const int lcol = (tid & 3) << 2;    // 0,4,8,12

    const float* Aptr = A + (size_t)(m0 + lrow) * DIM + lcol;
    const float* Wptr = W + (size_t)(n0 + lrow) * DIM + lcol;

    float acc[TM][TN];
#pragma unroll
    for (int i = 0; i < TM; i++)
#pragma unroll
        for (int j = 0; j < TN; j++) acc[i][j] = 0.0f;

    for (int kk = 0; kk < DIM; kk += BK) {
        float4 a0 = *(const float4*)(Aptr + kk);
        float4 a1 = *(const float4*)(Aptr + (size_t)64 * DIM + kk);
        float4 b0 = *(const float4*)(Wptr + kk);

        As[lcol + 0][lrow] = a0.x;
        As[lcol + 1][lrow] = a0.y;
        As[lcol + 2][lrow] = a0.z;
        As[lcol + 3][lrow] = a0.w;
        As[lcol + 0][lrow + 64] = a1.x;
        As[lcol + 1][lrow + 64] = a1.y;
        As[lcol + 2][lrow + 64] = a1.z;
        As[lcol + 3][lrow + 64] = a1.w;
        Bs[lcol + 0][lrow] = b0.x;
        Bs[lcol + 1][lrow] = b0.y;
        Bs[lcol + 2][lrow] = b0.z;
        Bs[lcol + 3][lrow] = b0.w;
        __syncthreads();

#pragma unroll
        for (int k = 0; k < BK; k++) {
            float4 av0 = *(const float4*)&As[k][ty * TM];
            float4 av1 = *(const float4*)&As[k][ty * TM + 4];
            float4 bv  = *(const float4*)&Bs[k][tx * TN];
            float a[TM] = {av0.x, av0.y, av0.z, av0.w, av1.x, av1.y, av1.z, av1.w};
            float b[TN] = {bv.x, bv.y, bv.z, bv.w};
#pragma unroll
            for (int i = 0; i < TM; i++)
#pragma unroll
                for (int j = 0; j < TN; j++)
                    acc[i][j] = fmaf(a[i], b[j], acc[i][j]);
        }
        __syncthreads();
    }

    const int m_base = m0 + ty * TM;
    const int n_base = n0 + tx * TN;

    if (QKV) {
#pragma unroll
        for (int i = 0; i < TM; i++) {
            int m = m_base + i;
            int b = m / NWIN;
            int nn = m - b * NWIN;
#pragma unroll
            for (int j = 0; j < TN; j++) {
                int n = n_base + j;
                float val = acc[i][j] + bias[n];
                int which = n / DIM;
                int rem = n - which * DIM;
                int h = rem >> 5;
                int d = rem & 31;
                size_t idx = (((size_t)b * NH + h) * NWIN + nn) * HD + d;
                if (which == 0)      g_q[idx] = val * QK_SCALE;
                else if (which == 1) g_k[idx] = val;
                else                 g_v[idx] = val;
            }
        }
    } else {
#pragma unroll
        for (int i = 0; i < TM; i++) {
            int m = m_base + i;
            float4 o;
            o.x = acc[i][0] + bias[n_base + 0];
            o.y = acc[i][1] + bias[n_base + 1];
            o.z = acc[i][2] + bias[n_base + 2];
            o.w = acc[i][3] + bias[n_base + 3];
            *(float4*)&out[(size_t)m * DIM + n_base] = o;
        }
    }
}

// ---------------------------------------------------------------------------
// Attention: one block per (head h, window b). 256 threads.
//   S = q*k^T (q pre-scaled) + A_phi(h) + A_r(b,h); softmax rows; O = P*V.
// Biases computed on the fly from (i,j) -> (radius, azimuth).
// ---------------------------------------------------------------------------
__global__ __launch_bounds__(256) void attn_kernel(
    const float* __restrict__ Dptr,
    const float* __restrict__ a_p, const float* __restrict__ b_p,
    const float* __restrict__ a_r, const float* __restrict__ b_r)
{
    const int h = blockIdx.x;
    const int b = blockIdx.y;
    const int tid = threadIdx.x;

    __shared__ float qs[NWIN * 33];
    __shared__ float ks[NWIN * 33];
    __shared__ float vs[NWIN * 33];
    __shared__ float S[NWIN * NWIN];
    __shared__ float t_ap[13], t_bp[13], t_ar[13], t_br[13];

    const size_t base = ((size_t)b * NH + h) * NWIN * HD;

    if (tid < 13) {
        t_ap[tid] = a_p[tid * NH + h];
        t_bp[tid] = b_p[tid * NH + h];
        t_ar[tid] = a_r[tid * NH + h];
        t_br[tid] = b_r[tid * NH + h];
    }
    for (int t = tid; t < NWIN * HD; t += 256) {
        int r = t >> 5, c = t & 31;
        qs[r * 33 + c] = g_q[base + t];
        ks[r * 33 + c] = g_k[base + t];
        vs[r * 33 + c] = g_v[base + t];
    }
    const float Db = Dptr[b];
    __syncthreads();

    // S = scores + biases
    for (int t = tid; t < NWIN * NWIN; t += 256) {
        int i = t / NWIN;
        int j = t - i * NWIN;
        const float* qr = qs + i * 33;
        const float* kr = ks + j * 33;
        float dot = 0.0f;
#pragma unroll
        for (int d = 0; d < HD; d++) dot = fmaf(qr[d], kr[d], dot);

        int ih = i / WW, iw = i - ih * WW;
        int jh = j / WW, jw = j - jh * WW;
        int rr = ih - jh;           // radius in [-6, 6]
        int az = iw - jw;           // azimuth in [-6, 6]
        int ridx = rr < 0 ? rr + 13 : rr;   // python-style wrap (mod 13)
        int aidx = az < 0 ? az + 13 : az;

        float sph, cph;
        sincosf((float)az * (2.0f * PI_F / 56.0f), &sph, &cph);
        float srr, crr;
        sincosf(Db * (float)rr * (2.0f * PI_F / 224.0f), &srr, &crr);

        S[t] = dot + t_ap[aidx] * cph + t_bp[aidx] * sph
                   + t_ar[ridx] * crr + t_br[ridx] * srr;
    }
    __syncthreads();

    // softmax: one warp per row
    const int warp = tid >> 5, lane = tid & 31;
    for (int row = warp; row < NWIN; row += 8) {
        float* Sr = S + row * NWIN;
        float v0 = Sr[lane];
        float v1 = (lane + 32 < NWIN) ? Sr[lane + 32] : -1e30f;
        float mx = fmaxf(v0, v1);
#pragma unroll
        for (int o = 16; o; o >>= 1)
            mx = fmaxf(mx, __shfl_xor_sync(0xffffffffu, mx, o));
        float e0 = expf(v0 - mx);
        float e1 = (lane + 32 < NWIN) ? expf(v1 - mx) : 0.0f;
        float sm = e0 + e1;
#pragma unroll
        for (int o = 16; o; o >>= 1)
            sm += __shfl_xor_sync(0xffffffffu, sm, o);
        float inv = 1.0f / sm;
        Sr[lane] = e0 * inv;
        if (lane + 32 < NWIN) Sr[lane + 32] = e1 * inv;
    }
    __syncthreads();

    // O = P * V -> ctx layout (b, n, h*32 + d) for the proj GEMM
    float* ctx = g_ctx + ((size_t)b * NWIN) * DIM + h * HD;
    for (int t = tid; t < NWIN * HD; t += 256) {
        int n = t >> 5, d = t & 31;
        const float* Pr = S + n * NWIN;
        float o = 0.0f;
#pragma unroll
        for (int m2 = 0; m2 < NWIN; m2++)
            o = fmaf(Pr[m2], vs[m2 * 33 + d], o);
        ctx[n * DIM + d] = o;
    }
}

// ---------------------------------------------------------------------------
extern "C" void kernel_launch(void* const* d_in, const int* in_sizes, int n_in,
                              void* d_out, int out_size)
{
    const float* x      = (const float*)d_in[0];
    const float* D      = (const float*)d_in[1];
    const float* qkv_w  = (const float*)d_in[2];
    const float* qkv_b  = (const float*)d_in[3];
    const float* proj_w = (const float*)d_in[4];
    const float* proj_b = (const float*)d_in[5];
    const float* a_p    = (const float*)d_in[6];
    const float* b_p    = (const float*)d_in[7];
    const float* a_r    = (const float*)d_in[8];
    const float* b_r    = (const float*)d_in[9];
    float* out = (float*)d_out;

    gemm_kernel<true><<<dim3(3 * DIM / BN, MROWS / BM), 256>>>(x, qkv_w, qkv_b, nullptr);
    attn_kernel<<<dim3(NH, BATCH), 256>>>(D, a_p, b_p, a_r, b_r);
    gemm_kernel<false><<<dim3(DIM / BN, MROWS / BM), 256>>>(nullptr, proj_w, proj_b, out);
}

// round 10
// speedup vs baseline: 1.0018x; 1.0005x over previous
#include <cuda_runtime.h>

// ---------------------------------------------------------------------------
// WindowAttention: x(2048,49,192) -> qkv gemm -> 6-head window attention with
// azimuthal + radial sinusoidal biases -> proj gemm.
// Round 4: correct fp32 baseline, tiled SGEMMs + fused per-(b,h) attention.
// ---------------------------------------------------------------------------

#define WH 7
#define WW 7
#define NWIN 49
#define NH 6
#define HD 32
#define DIM 192
#define BATCH 2048
#define MROWS (BATCH * NWIN)          // 100352
#define QK_SCALE 0.17677669529663687f // 32^-0.5
#define PI_F 3.14159265358979323846f

// Scratch (allocation-free rule: __device__ globals)
__device__ float g_q[(size_t)BATCH * NH * NWIN * HD];
__device__ float g_k[(size_t)BATCH * NH * NWIN * HD];
__device__ float g_v[(size_t)BATCH * NH * NWIN * HD];
__device__ float g_ctx[(size_t)MROWS * DIM];

// ---------------------------------------------------------------------------
// Tiled SGEMM: out[m][n] = sum_k A[m][k] * W[n][k] (+ bias[n])
// BM=128, BN=64, BK=16, 256 threads, 8x4 per-thread tile.
// QKV=true: A = x, epilogue scatters into g_q (scaled), g_k, g_v.
// QKV=false: A = g_ctx, epilogue writes d_out with bias.
// All dims divide tiles exactly (100352 = 784*128, 576 = 9*64, 192 = 3*64,
// K = 192 = 12*16) -> no bounds checks.
// ---------------------------------------------------------------------------
#define BM 128
#define BN 64
#define BK 16
#define TM 8
#define TN 4

template <bool QKV>
__global__ __launch_bounds__(256) void gemm_kernel(
    const float* __restrict__ Ain, const float* __restrict__ W,
    const float* __restrict__ bias, float* __restrict__ out)
{
    const float* A = QKV ? Ain : g_ctx;

    __shared__ float As[BK][BM];
    __shared__ float Bs[BK][BN];

    const int tid = threadIdx.x;
    const int ty = tid >> 4;        // 0..15
    const int tx = tid & 15;        // 0..15
    const int m0 = blockIdx.y * BM;
    const int n0 = blockIdx.x * BN;

    const int lrow = tid >> 2;          // 0..63
    const int lcol = (tid & 3) << 2;    // 0,4,8,12

    const float* Aptr = A + (size_t)(m0 + lrow) * DIM + lcol;
    const float* Wptr = W + (size_t)(n0 + lrow) * DIM + lcol;

    float acc[TM][TN];
#pragma unroll
    for (int i = 0; i < TM; i++)
#pragma unroll
        for (int j = 0; j < TN; j++) acc[i][j] = 0.0f;

    for (int kk = 0; kk < DIM; kk += BK) {
        float4 a0 = *(const float4*)(Aptr + kk);
        float4 a1 = *(const float4*)(Aptr + (size_t)64 * DIM + kk);
        float4 b0 = *(const float4*)(Wptr + kk);

        As[lcol + 0][lrow] = a0.x;
        As[lcol + 1][lrow] = a0.y;
        As[lcol + 2][lrow] = a0.z;
        As[lcol + 3][lrow] = a0.w;
        As[lcol + 0][lrow + 64] = a1.x;
        As[lcol + 1][lrow + 64] = a1.y;
        As[lcol + 2][lrow + 64] = a1.z;
        As[lcol + 3][lrow + 64] = a1.w;
        Bs[lcol + 0][lrow] = b0.x;
        Bs[lcol + 1][lrow] = b0.y;
        Bs[lcol + 2][lrow] = b0.z;
        Bs[lcol + 3][lrow] = b0.w;
        __syncthreads();

#pragma unroll
        for (int k = 0; k < BK; k++) {
            float4 av0 = *(const float4*)&As[k][ty * TM];
            float4 av1 = *(const float4*)&As[k][ty * TM + 4];
            float4 bv  = *(const float4*)&Bs[k][tx * TN];
            float a[TM] = {av0.x, av0.y, av0.z, av0.w, av1.x, av1.y, av1.z, av1.w};
            float b[TN] = {bv.x, bv.y, bv.z, bv.w};
#pragma unroll
            for (int i = 0; i < TM; i++)
#pragma unroll
                for (int j = 0; j < TN; j++)
                    acc[i][j] = fmaf(a[i], b[j], acc[i][j]);
        }
        __syncthreads();
    }

    const int m_base = m0 + ty * TM;
    const int n_base = n0 + tx * TN;

    if (QKV) {
#pragma unroll
        for (int i = 0; i < TM; i++) {
            int m = m_base + i;
            int b = m / NWIN;
            int nn = m - b * NWIN;
#pragma unroll
            for (int j = 0; j < TN; j++) {
                int n = n_base + j;
                float val = acc[i][j] + bias[n];
                int which = n / DIM;
                int rem = n - which * DIM;
                int h = rem >> 5;
                int d = rem & 31;
                size_t idx = (((size_t)b * NH + h) * NWIN + nn) * HD + d;
                if (which == 0)      g_q[idx] = val * QK_SCALE;
                else if (which == 1) g_k[idx] = val;
                else                 g_v[idx] = val;
            }
        }
    } else {
#pragma unroll
        for (int i = 0; i < TM; i++) {
            int m = m_base + i;
            float4 o;
            o.x = acc[i][0] + bias[n_base + 0];
            o.y = acc[i][1] + bias[n_base + 1];
            o.z = acc[i][2] + bias[n_base + 2];
            o.w = acc[i][3] + bias[n_base + 3];
            *(float4*)&out[(size_t)m * DIM + n_base] = o;
        }
    }
}

// ---------------------------------------------------------------------------
// Attention: one block per (head h, window b). 256 threads.
//   S = q*k^T (q pre-scaled) + A_phi(h) + A_r(b,h); softmax rows; O = P*V.
// Biases computed on the fly from (i,j) -> (radius, azimuth).
// ---------------------------------------------------------------------------
__global__ __launch_bounds__(256) void attn_kernel(
    const float* __restrict__ Dptr,
    const float* __restrict__ a_p, const float* __restrict__ b_p,
    const float* __restrict__ a_r, const float* __restrict__ b_r)
{
    const int h = blockIdx.x;
    const int b = blockIdx.y;
    const int tid = threadIdx.x;

    __shared__ float qs[NWIN * 33];
    __shared__ float ks[NWIN * 33];
    __shared__ float vs[NWIN * 33];
    __shared__ float S[NWIN * NWIN];
    __shared__ float t_ap[13], t_bp[13], t_ar[13], t_br[13];

    const size_t base = ((size_t)b * NH + h) * NWIN * HD;

    if (tid < 13) {
        t_ap[tid] = a_p[tid * NH + h];
        t_bp[tid] = b_p[tid * NH + h];
        t_ar[tid] = a_r[tid * NH + h];
        t_br[tid] = b_r[tid * NH + h];
    }
    for (int t = tid; t < NWIN * HD; t += 256) {
        int r = t >> 5, c = t & 31;
        qs[r * 33 + c] = g_q[base + t];
        ks[r * 33 + c] = g_k[base + t];
        vs[r * 33 + c] = g_v[base + t];
    }
    const float Db = Dptr[b];
    __syncthreads();

    // S = scores + biases
    for (int t = tid; t < NWIN * NWIN; t += 256) {
        int i = t / NWIN;
        int j = t - i * NWIN;
        const float* qr = qs + i * 33;
        const float* kr = ks + j * 33;
        float dot = 0.0f;
#pragma unroll
        for (int d = 0; d < HD; d++) dot = fmaf(qr[d], kr[d], dot);

        int ih = i / WW, iw = i - ih * WW;
        int jh = j / WW, jw = j - jh * WW;
        int rr = ih - jh;           // radius in [-6, 6]
        int az = iw - jw;           // azimuth in [-6, 6]
        int ridx = rr < 0 ? rr + 13 : rr;   // python-style wrap (mod 13)
        int aidx = az < 0 ? az + 13 : az;

        float sph, cph;
        sincosf((float)az * (2.0f * PI_F / 56.0f), &sph, &cph);
        float srr, crr;
        sincosf(Db * (float)rr * (2.0f * PI_F / 224.0f), &srr, &crr);

        S[t] = dot + t_ap[aidx] * cph + t_bp[aidx] * sph
                   + t_ar[ridx] * crr + t_br[ridx] * srr;
    }
    __syncthreads();

    // softmax: one warp per row
    const int warp = tid >> 5, lane = tid & 31;
    for (int row = warp; row < NWIN; row += 8) {
        float* Sr = S + row * NWIN;
        float v0 = Sr[lane];
        float v1 = (lane + 32 < NWIN) ? Sr[lane + 32] : -1e30f;
        float mx = fmaxf(v0, v1);
#pragma unroll
        for (int o = 16; o; o >>= 1)
            mx = fmaxf(mx, __shfl_xor_sync(0xffffffffu, mx, o));
        float e0 = expf(v0 - mx);
        float e1 = (lane + 32 < NWIN) ? expf(v1 - mx) : 0.0f;
        float sm = e0 + e1;
#pragma unroll
        for (int o = 16; o; o >>= 1)
            sm += __shfl_xor_sync(0xffffffffu, sm, o);
        float inv = 1.0f / sm;
        Sr[lane] = e0 * inv;
        if (lane + 32 < NWIN) Sr[lane + 32] = e1 * inv;
    }
    __syncthreads();

    // O = P * V -> ctx layout (b, n, h*32 + d) for the proj GEMM
    float* ctx = g_ctx + ((size_t)b * NWIN) * DIM + h * HD;
    for (int t = tid; t < NWIN * HD; t += 256) {
        int n = t >> 5, d = t & 31;
        const float* Pr = S + n * NWIN;
        float o = 0.0f;
#pragma unroll
        for (int m2 = 0; m2 < NWIN; m2++)
            o = fmaf(Pr[m2], vs[m2 * 33 + d], o);
        ctx[n * DIM + d] = o;
    }
}

// ---------------------------------------------------------------------------
extern "C" void kernel_launch(void* const* d_in, const int* in_sizes, int n_in,
                              void* d_out, int out_size)
{
    const float* x      = (const float*)d_in[0];
    const float* D      = (const float*)d_in[1];
    const float* qkv_w  = (const float*)d_in[2];
    const float* qkv_b  = (const float*)d_in[3];
    const float* proj_w = (const float*)d_in[4];
    const float* proj_b = (const float*)d_in[5];
    const float* a_p    = (const float*)d_in[6];
    const float* b_p    = (const float*)d_in[7];
    const float* a_r    = (const float*)d_in[8];
    const float* b_r    = (const float*)d_in[9];
    float* out = (float*)d_out;

    gemm_kernel<true><<<dim3(3 * DIM / BN, MROWS / BM), 256>>>(x, qkv_w, qkv_b, nullptr);
    attn_kernel<<<dim3(NH, BATCH), 256>>>(D, a_p, b_p, a_r, b_r);
    gemm_kernel<false><<<dim3(DIM / BN, MROWS / BM), 256>>>(nullptr, proj_w, proj_b, out);
}